// round 13
// baseline (speedup 1.0000x reference)
#include <cuda_runtime.h>
#include <cuda_fp16.h>
#include <cstdint>
#include <cstddef>

#define DEVINL __device__ __forceinline__

constexpr int MROWS = 16384;
constexpr int KTOT  = 1024;
constexpr int NCOLS = 1024;

constexpr int BM = 128, BN = 128, BK = 64;
constexpr int STAGES = 3;
constexpr int TPB = 256;
constexpr int NCHUNK = KTOT / BK;               // 16

constexpr int A_BYTES = BM * BK * 2;            // 16 KB fp16
constexpr int B_BYTES = BN * BK * 2;            // 16 KB
constexpr int STAGE_BYTES = A_BYTES + B_BYTES;  // 32 KB
constexpr int SMEM_TOTAL = STAGES * STAGE_BYTES; // 96 KB (x2 CTAs = 192 KB/SM)

// Static device scratch: only W now (A converts in-kernel, in-register)
__device__ __half g_wt[(size_t)NCOLS * KTOT];   // W quantized, [n][k] K-major

// ---------------------------------------------------------------- helpers
DEVINL uint32_t smem_u32(const void* p) {
    uint32_t r;
    asm("{ .reg .u64 t; cvta.to.shared.u64 t, %1; cvt.u32.u64 %0, t; }"
        : "=r"(r) : "l"(p));
    return r;
}
DEVINL uint32_t swz(uint32_t off) { return off ^ ((off >> 3) & 0x70); }
DEVINL void cp_async16(uint32_t s, const void* g) {
    asm volatile("cp.async.cg.shared.global [%0], [%1], 16;"
                 :: "r"(s), "l"(g) : "memory");
}
DEVINL void cp_commit() { asm volatile("cp.async.commit_group;" ::: "memory"); }
template <int N> DEVINL void cp_wait() {
    asm volatile("cp.async.wait_group %0;" :: "n"(N) : "memory");
}
DEVINL void ldg128(float4& v, const float* p) {
    asm volatile("ld.global.nc.v4.f32 {%0,%1,%2,%3}, [%4];"
                 : "=f"(v.x), "=f"(v.y), "=f"(v.z), "=f"(v.w) : "l"(p));
}
DEVINL void sts128(uint32_t a, uint32_t x, uint32_t y, uint32_t z, uint32_t w) {
    asm volatile("st.shared.v4.b32 [%0], {%1,%2,%3,%4};"
                 :: "r"(a), "r"(x), "r"(y), "r"(z), "r"(w));
}
DEVINL void ldsm_x4(uint32_t* r, uint32_t addr) {
    asm volatile("ldmatrix.sync.aligned.m8n8.x4.shared.b16 {%0,%1,%2,%3}, [%4];"
                 : "=r"(r[0]), "=r"(r[1]), "=r"(r[2]), "=r"(r[3]) : "r"(addr));
}
DEVINL void mma16816(float* c, const uint32_t* a, const uint32_t* b) {
    asm volatile(
        "mma.sync.aligned.m16n8k16.row.col.f32.f16.f16.f32 "
        "{%0,%1,%2,%3}, {%4,%5,%6,%7}, {%8,%9}, {%0,%1,%2,%3};"
        : "+f"(c[0]), "+f"(c[1]), "+f"(c[2]), "+f"(c[3])
        : "r"(a[0]), "r"(a[1]), "r"(a[2]), "r"(a[3]), "r"(b[0]), "r"(b[1]));
}
DEVINL uint32_t pack_half2(float x, float y) {
    __half2 h = __floats2half2_rn(x, y);
    return *reinterpret_cast<uint32_t*>(&h);
}

// -------------------------------------------- W quantize + transpose (tiny)
__global__ void quant_w_kernel(const float* __restrict__ w) {
    __shared__ __half tile[32][33];
    const int n0 = (blockIdx.x & 31) * 32;
    const int k0 = (blockIdx.x >> 5) * 32;
    const int tx = threadIdx.x & 31;
    const int ty = threadIdx.x >> 5;
    #pragma unroll
    for (int i = ty; i < 32; i += 8) {
        float x = w[(size_t)(k0 + i) * NCOLS + n0 + tx];
        x = fminf(fmaxf(x, -0.5f), 0.5f);     // clip [-1+delta, 1-delta]
        float y = rintf(x * 2.0f) * 0.5f;     // round-half-even, step 0.5
        tile[i][tx] = __float2half_rn(y);     // exact in fp16
    }
    __syncthreads();
    #pragma unroll
    for (int i = ty; i < 32; i += 8)
        g_wt[(size_t)(n0 + i) * KTOT + k0 + tx] = tile[tx][i];
}

// ------------------------------------------------------------- main GEMM
// R4 mainloop; A converted fp32->fp16 in-register on the global->smem path.
__global__ void __launch_bounds__(TPB, 2)
gemm_hmma_kernel(const float* __restrict__ A, float* __restrict__ C) {
    extern __shared__ char smem[];
    const uint32_t sb = smem_u32(smem);
    const int tid  = threadIdx.x;
    const int lane = tid & 31;
    const int wid  = tid >> 5;
    const int warpM = wid & 3;
    const int warpN = wid >> 2;

    const int m0 = blockIdx.y * BM;
    const int n0 = blockIdx.x * BN;

    const char* bG = (const char*)(g_wt + (size_t)n0 * KTOT);

    // per-thread mapping (rows 0..31 per pass, 4 passes = 128 rows)
    const int lr = tid >> 3;                       // row 0..31
    const int lc8 = (tid & 7) * 8;                 // fp32-element col within chunk
    const uint32_t ld_sw0 = swz(lr * 128 + (tid & 7) * 16);  // fp16/byte offset

    const float* aRow = A + (size_t)(m0 + lr) * KTOT + lc8;

    // B-only cp.async stage loader (4x 16B per thread)
    auto load_stage_B = [&](int kc, int s) {
        const uint32_t bS = sb + s * STAGE_BYTES + A_BYTES;
        const char* bg = bG + (size_t)lr * (KTOT * 2) + kc * (BK * 2) + (tid & 7) * 16;
        #pragma unroll
        for (int it = 0; it < 4; it++)
            cp_async16(bS + ld_sw0 + it * 4096, bg + (size_t)it * 32 * KTOT * 2);
    };
    // A convert unit u (32-row band): LDG 2x float4 of chunk kc
    auto ldgA = [&](float4& v0, float4& v1, int kc, int u) {
        const float* p = aRow + kc * BK + (size_t)u * 32 * KTOT;
        ldg128(v0, p);
        ldg128(v1, p + 4);
    };
    auto stsA = [&](const float4& v0, const float4& v1, int s, int u) {
        sts128(sb + s * STAGE_BYTES + ld_sw0 + u * 4096,
               pack_half2(v0.x, v0.y), pack_half2(v0.z, v0.w),
               pack_half2(v1.x, v1.y), pack_half2(v1.z, v1.w));
    };

    uint32_t aBase[2], bBase[4];
    #pragma unroll
    for (int mi = 0; mi < 2; mi++) {
        const int row = warpM * 32 + mi * 16 + (lane & 15);
        const int ko  = (lane >> 4) * 8;
        aBase[mi] = swz(row * 128 + ko * 2);
    }
    #pragma unroll
    for (int nj = 0; nj < 4; nj++) {
        const int row = warpN * 64 + nj * 16 + ((lane >> 4) << 3) + (lane & 7);
        const int ko  = ((lane >> 3) & 1) * 8;
        bBase[nj] = swz(row * 128 + ko * 2) + A_BYTES;
    }

    // prologue: B cp.async for stages 0,1; A convert+store for stages 0,1
    #pragma unroll
    for (int s = 0; s < STAGES - 1; s++) { load_stage_B(s, s); cp_commit(); }
    #pragma unroll
    for (int s = 0; s < STAGES - 1; s++) {
        #pragma unroll
        for (int u = 0; u < 4; u++) {
            float4 v0, v1;
            ldgA(v0, v1, s, u);
            stsA(v0, v1, s, u);
        }
    }

    float acc[2][8][4] = {};

    for (int kc = 0; kc < NCHUNK; kc++) {
        cp_wait<1>();          // B(kc) landed (this thread)
        __syncthreads();       // all threads' B cp.async + A STS for kc visible

        const int kn = kc + 2;                  // chunk converted this iter
        const int sn = (kc + 2) % STAGES;       // its stage slot (freed by bar)
        if (kn < NCHUNK) load_stage_B(kn, sn);
        cp_commit();                            // uniform group accounting

        const uint32_t stS = sb + (kc % STAGES) * STAGE_BYTES;

        float4 p0, p1;                          // in-flight A unit
        if (kn < NCHUNK) ldgA(p0, p1, kn, 0);

        #pragma unroll
        for (int ki = 0; ki < BK / 16; ki++) {
            const uint32_t kOff = ki * 32;
            uint32_t afr[2][4], bfr[4][4];
            #pragma unroll
            for (int mi = 0; mi < 2; mi++)
                ldsm_x4(afr[mi], stS + (aBase[mi] ^ kOff));
            #pragma unroll
            for (int nj = 0; nj < 4; nj++)
                ldsm_x4(bfr[nj], stS + (bBase[nj] ^ kOff));
            #pragma unroll
            for (int mi = 0; mi < 2; mi++)
                #pragma unroll
                for (int nj = 0; nj < 8; nj++)
                    mma16816(acc[mi][nj], afr[mi], &bfr[nj >> 1][(nj & 1) * 2]);

            // drain unit ki, launch unit ki+1 (LDG covered by next MMA block)
            if (kn < NCHUNK) {
                stsA(p0, p1, sn, ki);
                if (ki < 3) ldgA(p0, p1, kn, ki + 1);
            }
        }
    }

    // ---- epilogue: direct coalesced-by-quad float2 stores
    float* cBase = C + (size_t)(m0 + warpM * 32) * NCOLS + n0 + warpN * 64;
    const int cr = lane >> 2;
    const int cc = (lane & 3) * 2;
    #pragma unroll
    for (int mi = 0; mi < 2; mi++) {
        #pragma unroll
        for (int nj = 0; nj < 8; nj++) {
            float* q0 = cBase + (size_t)(mi * 16 + cr) * NCOLS + nj * 8 + cc;
            float* q1 = q0 + 8 * NCOLS;
            *reinterpret_cast<float2*>(q0) = make_float2(acc[mi][nj][0], acc[mi][nj][1]);
            *reinterpret_cast<float2*>(q1) = make_float2(acc[mi][nj][2], acc[mi][nj][3]);
        }
    }
}

// ---------------------------------------------------------------- launch
extern "C" void kernel_launch(void* const* d_in, const int* in_sizes, int n_in,
                              void* d_out, int out_size) {
    (void)in_sizes; (void)n_in; (void)out_size;
    const float* A = (const float*)d_in[0];   // [16384, 1024] fp32
    const float* W = (const float*)d_in[1];   // [1024, 1024] fp32
    float* C = (float*)d_out;                 // [16384, 1024] fp32

    quant_w_kernel<<<(NCOLS / 32) * (KTOT / 32), 256>>>(W);

    cudaFuncSetAttribute(gemm_hmma_kernel,
                         cudaFuncAttributeMaxDynamicSharedMemorySize, SMEM_TOTAL);
    gemm_hmma_kernel<<<dim3(NCOLS / BN, MROWS / BM), TPB, SMEM_TOTAL>>>(A, C);
}

// round 14
// speedup vs baseline: 1.5714x; 1.5714x over previous
#include <cuda_runtime.h>
#include <cuda_fp16.h>
#include <cstdint>
#include <cstddef>

#define DEVINL __device__ __forceinline__

constexpr int MROWS = 16384;
constexpr int KTOT  = 1024;
constexpr int NCOLS = 1024;

// GEMM tiling: CTA 128x128, warp tile 32x64 (8 warps: 4 over M, 2 over N), 2 CTAs/SM
constexpr int BM = 128, BN = 128, BK = 64;      // BK in fp16 elements (128B row)
constexpr int STAGES = 3;
constexpr int TPB = 256;
constexpr int NCHUNK = KTOT / BK;               // 16

constexpr int A_BYTES = BM * BK * 2;            // 16 KB
constexpr int B_BYTES = BN * BK * 2;            // 16 KB
constexpr int STAGE_BYTES = A_BYTES + B_BYTES;  // 32 KB
constexpr int SMEM_TOTAL = STAGES * STAGE_BYTES; // 96 KB (x2 CTAs = 192 KB/SM)

// Static device scratch (allocation-free rule)
__device__ __half g_ah[(size_t)MROWS * KTOT];   // A converted to fp16
__device__ __half g_wt[(size_t)NCOLS * KTOT];   // W quantized, [n][k] K-major

// prep split: conv handles 2 "units" per thread; 1 unit = 8 fp32 -> 8 fp16
constexpr int CONV_BLOCKS  = 4096;   // 4096*256 thr * 2 units * 8 = 16.8M floats
constexpr int QUANT_BLOCKS = (NCOLS / 32) * (KTOT / 32);  // 1024
constexpr int CONV_STRIDE  = CONV_BLOCKS * 256;           // units

// ---------------------------------------------------------------- helpers
DEVINL uint32_t smem_u32(const void* p) {
    uint32_t r;
    asm("{ .reg .u64 t; cvta.to.shared.u64 t, %1; cvt.u32.u64 %0, t; }"
        : "=r"(r) : "l"(p));
    return r;
}
DEVINL uint32_t swz(uint32_t off) {            // SW128: bits[6:4] ^= bits[9:7]
    return off ^ ((off >> 3) & 0x70);
}
DEVINL void cp_async16(uint32_t s, const void* g) {
    asm volatile("cp.async.cg.shared.global [%0], [%1], 16;"
                 :: "r"(s), "l"(g) : "memory");
}
DEVINL void cp_commit() {
    asm volatile("cp.async.commit_group;" ::: "memory");
}
template <int N> DEVINL void cp_wait() {
    asm volatile("cp.async.wait_group %0;" :: "n"(N) : "memory");
}
DEVINL void ldsm_x4(uint32_t* r, uint32_t addr) {
    asm volatile("ldmatrix.sync.aligned.m8n8.x4.shared.b16 {%0,%1,%2,%3}, [%4];"
                 : "=r"(r[0]), "=r"(r[1]), "=r"(r[2]), "=r"(r[3]) : "r"(addr));
}
DEVINL void mma16816(float* c, const uint32_t* a, const uint32_t* b) {
    asm volatile(
        "mma.sync.aligned.m16n8k16.row.col.f32.f16.f16.f32 "
        "{%0,%1,%2,%3}, {%4,%5,%6,%7}, {%8,%9}, {%0,%1,%2,%3};"
        : "+f"(c[0]), "+f"(c[1]), "+f"(c[2]), "+f"(c[3])
        : "r"(a[0]), "r"(a[1]), "r"(a[2]), "r"(a[3]), "r"(b[0]), "r"(b[1]));
}
DEVINL uint32_t pack_half2(float x, float y) {
    __half2 h = __floats2half2_rn(x, y);
    return *reinterpret_cast<uint32_t*>(&h);
}
DEVINL void ldg128nc(float4& v, const float* p) {
    asm volatile("ld.global.nc.v4.f32 {%0,%1,%2,%3}, [%4];"
                 : "=f"(v.x), "=f"(v.y), "=f"(v.z), "=f"(v.w) : "l"(p));
}
DEVINL void stg128cs(void* p, uint32_t x, uint32_t y, uint32_t z, uint32_t w) {
    asm volatile("st.global.cs.v4.b32 [%0], {%1,%2,%3,%4};"
                 :: "l"(p), "r"(x), "r"(y), "r"(z), "r"(w) : "memory");
}

// -------------------------------------------- merged prep kernel
// blocks [0, CONV_BLOCKS):             A fp32 -> fp16 (2 units/thread, MLP=4,
//                                      128-bit streaming stores)
// blocks [CONV_BLOCKS, +QUANT_BLOCKS): W quantize + transpose
__global__ void prep_kernel(const float* __restrict__ a,
                            const float* __restrict__ w) {
    const int bid = blockIdx.x;
    const int t   = threadIdx.x;

    if (bid < CONV_BLOCKS) {
        const size_t u0 = (size_t)bid * 256 + t;          // unit index
        const size_t u1 = u0 + CONV_STRIDE;
        const float* p0 = a + u0 * 8;
        const float* p1 = a + u1 * 8;
        float4 v0a, v0b, v1a, v1b;                        // 4 independent LDGs
        ldg128nc(v0a, p0);
        ldg128nc(v0b, p0 + 4);
        ldg128nc(v1a, p1);
        ldg128nc(v1b, p1 + 4);
        stg128cs(g_ah + u0 * 8,
                 pack_half2(v0a.x, v0a.y), pack_half2(v0a.z, v0a.w),
                 pack_half2(v0b.x, v0b.y), pack_half2(v0b.z, v0b.w));
        stg128cs(g_ah + u1 * 8,
                 pack_half2(v1a.x, v1a.y), pack_half2(v1a.z, v1a.w),
                 pack_half2(v1b.x, v1b.y), pack_half2(v1b.z, v1b.w));
    } else {
        __shared__ __half tile[32][33];
        const int tb = bid - CONV_BLOCKS;
        const int n0 = (tb & 31) * 32;
        const int k0 = (tb >> 5) * 32;
        const int tx = t & 31;
        const int ty = t >> 5;
        #pragma unroll
        for (int i = ty; i < 32; i += 8) {
            float x = w[(size_t)(k0 + i) * NCOLS + n0 + tx];
            x = fminf(fmaxf(x, -0.5f), 0.5f);     // clip [-1+delta, 1-delta]
            float y = rintf(x * 2.0f) * 0.5f;     // round-half-even, step 0.5
            tile[i][tx] = __float2half_rn(y);     // exact in fp16
        }
        __syncthreads();
        #pragma unroll
        for (int i = ty; i < 32; i += 8) {
            g_wt[(size_t)(n0 + i) * KTOT + k0 + tx] = tile[tx][i];
        }
    }
}

// ------------------------------------------------------------- main GEMM
// (exact R4 kernel — proven 83.7 us, tensor 67.2%; do not modify)
__global__ void __launch_bounds__(TPB, 2)
gemm_hmma_kernel(float* __restrict__ C) {
    extern __shared__ char smem[];
    const uint32_t sb = smem_u32(smem);
    const int tid  = threadIdx.x;
    const int lane = tid & 31;
    const int wid  = tid >> 5;
    const int warpM = wid & 3;    // 4 warps over M -> 32 rows each
    const int warpN = wid >> 2;   // 2 warps over N -> 64 cols each

    const int m0 = blockIdx.y * BM;
    const int n0 = blockIdx.x * BN;

    const char* aG = (const char*)(g_ah + (size_t)m0 * KTOT);
    const char* bG = (const char*)(g_wt + (size_t)n0 * KTOT);

    // per-thread cp.async mapping: 32 rows x 8 chunks of 16B per pass
    const int lr = tid >> 3;             // row 0..31
    const int lc = (tid & 7) * 16;       // byte offset within 128B row
    const uint32_t ld_sw0 = swz(lr * 128 + lc);   // same XOR mask all passes

    auto load_stage = [&](int kc, int s) {
        const uint32_t aS = sb + s * STAGE_BYTES;
        const uint32_t bS = aS + A_BYTES;
        const char* ag = aG + (size_t)lr * (KTOT * 2) + kc * (BK * 2) + lc;
        const char* bg = bG + (size_t)lr * (KTOT * 2) + kc * (BK * 2) + lc;
        #pragma unroll
        for (int it = 0; it < 4; it++) {
            const uint32_t sw = ld_sw0 + it * 32 * 128;
            cp_async16(aS + sw, ag + (size_t)it * 32 * KTOT * 2);
            cp_async16(bS + sw, bg + (size_t)it * 32 * KTOT * 2);
        }
    };

    // hoisted ldmatrix address bases (offset within stage, ki=0)
    uint32_t aBase[2], bBase[4];
    #pragma unroll
    for (int mi = 0; mi < 2; mi++) {
        const int row = warpM * 32 + mi * 16 + (lane & 15);
        const int ko  = (lane >> 4) * 8;
        aBase[mi] = swz(row * 128 + ko * 2);
    }
    #pragma unroll
    for (int nj = 0; nj < 4; nj++) {
        const int row = warpN * 64 + nj * 16 + ((lane >> 4) << 3) + (lane & 7);
        const int ko  = ((lane >> 3) & 1) * 8;
        bBase[nj] = swz(row * 128 + ko * 2) + A_BYTES;
    }

    // prologue: stages 0..STAGES-2
    #pragma unroll
    for (int s = 0; s < STAGES - 1; s++) {
        load_stage(s, s);
        cp_commit();
    }

    float acc[2][8][4] = {};

    for (int kc = 0; kc < NCHUNK; kc++) {
        cp_wait<STAGES - 2>();
        __syncthreads();   // stage kc ready for all; prev compute finished

        // prefetch stage kc+STAGES-1 into the slot just freed
        if (kc + STAGES - 1 < NCHUNK)
            load_stage(kc + STAGES - 1, (kc + STAGES - 1) % STAGES);
        cp_commit();       // empty groups keep group counts uniform

        const uint32_t stS = sb + (kc % STAGES) * STAGE_BYTES;

        #pragma unroll
        for (int ki = 0; ki < BK / 16; ki++) {           // 4 k16 steps
            const uint32_t kOff = ki * 32;               // 16 fp16 = 32 B; XOR-safe
            uint32_t afr[2][4], bfr[4][4];
            #pragma unroll
            for (int mi = 0; mi < 2; mi++)
                ldsm_x4(afr[mi], stS + (aBase[mi] ^ kOff));
            #pragma unroll
            for (int nj = 0; nj < 4; nj++)
                ldsm_x4(bfr[nj], stS + (bBase[nj] ^ kOff));
            #pragma unroll
            for (int mi = 0; mi < 2; mi++)
                #pragma unroll
                for (int nj = 0; nj < 8; nj++)
                    mma16816(acc[mi][nj], afr[mi], &bfr[nj >> 1][(nj & 1) * 2]);
        }
    }

    // ---- epilogue: direct coalesced-by-quad float2 stores
    float* cBase = C + (size_t)(m0 + warpM * 32) * NCOLS + n0 + warpN * 64;
    const int cr = lane >> 2;
    const int cc = (lane & 3) * 2;
    #pragma unroll
    for (int mi = 0; mi < 2; mi++) {
        #pragma unroll
        for (int nj = 0; nj < 8; nj++) {
            float* p0 = cBase + (size_t)(mi * 16 + cr) * NCOLS + nj * 8 + cc;
            float* p1 = p0 + 8 * NCOLS;
            *reinterpret_cast<float2*>(p0) = make_float2(acc[mi][nj][0], acc[mi][nj][1]);
            *reinterpret_cast<float2*>(p1) = make_float2(acc[mi][nj][2], acc[mi][nj][3]);
        }
    }
}

// ---------------------------------------------------------------- launch
extern "C" void kernel_launch(void* const* d_in, const int* in_sizes, int n_in,
                              void* d_out, int out_size) {
    (void)in_sizes; (void)n_in; (void)out_size;
    const float* A = (const float*)d_in[0];   // [16384, 1024] fp32
    const float* W = (const float*)d_in[1];   // [1024, 1024] fp32
    float* C = (float*)d_out;                 // [16384, 1024] fp32

    prep_kernel<<<CONV_BLOCKS + QUANT_BLOCKS, 256>>>(A, W);

    cudaFuncSetAttribute(gemm_hmma_kernel,
                         cudaFuncAttributeMaxDynamicSharedMemorySize, SMEM_TOTAL);
    gemm_hmma_kernel<<<dim3(NCOLS / BN, MROWS / BM), TPB, SMEM_TOTAL>>>(C);
}